// round 3
// baseline (speedup 1.0000x reference)
#include <cuda_runtime.h>
#include <cuda_bf16.h>
#include <climits>
#include <cstdint>

// Problem constants (fixed by dataset)
#define NN 20000
#define EE 320000
#define ET (EE + NN)   // edges incl. self loops
#define HC 256

// ---------------- scratch (no allocations allowed) ----------------
__device__ float g_xl[NN * HC];
__device__ float g_xr[NN * HC];
__device__ float g_h[NN * HC];
__device__ float g_agg[NN * HC];
__device__ float g_score[ET * 4];
__device__ int   g_smax[NN * 4];
__device__ float g_denom[NN * 4];
__device__ float g_gvec[HC];
__device__ int   g_is64;

// ---------------- helpers ----------------
__device__ __forceinline__ int f2o(float f) {
    int i = __float_as_int(f);
    return i >= 0 ? i : i ^ 0x7FFFFFFF;
}
__device__ __forceinline__ float o2f(int i) {
    return __int_as_float(i >= 0 ? i : i ^ 0x7FFFFFFF);
}

// edge_index may be int32 (JAX default, x64 disabled) or int64. Load through probe flag.
__device__ __forceinline__ int load_idx(const void* ei, int pos) {
    if (g_is64) return (int)((const long long*)ei)[pos];
    return ((const int*)ei)[pos];
}

// ---------------- dtype probe: int64 stored little-endian has zero high words ----------------
__global__ void k_detect(const int* __restrict__ ei32) {
    // single warp; check odd int32 positions 1,3,...,4095
    int lane = threadIdx.x;
    int nz = 0;
    for (int i = lane * 2 + 1; i < 4096; i += 64) nz |= (ei32[i] != 0);
#pragma unroll
    for (int o = 16; o; o >>= 1) nz |= __shfl_xor_sync(0xFFFFFFFFu, nz, o);
    if (lane == 0) g_is64 = nz ? 0 : 1;
}

// ---------------- init: zero accumulators, set smax=-inf ----------------
__global__ void k_init(int n) {
    int i = blockIdx.x * blockDim.x + threadIdx.x;
    int total = n * HC;
    for (int idx = i; idx < total; idx += gridDim.x * blockDim.x) g_agg[idx] = 0.f;
    if (i < n * 4) { g_smax[i] = INT_MIN; g_denom[i] = 0.f; }
    if (i < HC) g_gvec[i] = 0.f;
}

// ---------------- SGEMM: C[M x 256] = A[M x 256] @ B[256 x 256] ----------------
__global__ __launch_bounds__(256) void k_sgemm(const float* __restrict__ A,
                                               const float* __restrict__ B,
                                               float* __restrict__ C, int M) {
    constexpr int BM = 128, BN = 128, BK = 8, TM = 8, TN = 8;
    constexpr int K = 256, N = 256;
    __shared__ float As[BK][BM];
    __shared__ float Bs[BK][BN];
    const int tid = threadIdx.x;
    const int br = blockIdx.y * BM;
    const int bc = blockIdx.x * BN;
    const int tr = (tid / 16) * TM;
    const int tc = (tid % 16) * TN;
    const int arow = tid >> 1;
    const int acol = (tid & 1) * 4;
    const int brow = tid >> 5;
    const int bcol = (tid & 31) * 4;

    float acc[TM][TN];
#pragma unroll
    for (int i = 0; i < TM; i++)
#pragma unroll
        for (int j = 0; j < TN; j++) acc[i][j] = 0.f;

    for (int k0 = 0; k0 < K; k0 += BK) {
        float4 a4 = make_float4(0.f, 0.f, 0.f, 0.f);
        int gr = br + arow;
        if (gr < M)
            a4 = *reinterpret_cast<const float4*>(&A[(size_t)gr * K + k0 + acol]);
        As[acol + 0][arow] = a4.x;
        As[acol + 1][arow] = a4.y;
        As[acol + 2][arow] = a4.z;
        As[acol + 3][arow] = a4.w;
        float4 b4 = *reinterpret_cast<const float4*>(&B[(size_t)(k0 + brow) * N + bc + bcol]);
        *reinterpret_cast<float4*>(&Bs[brow][bcol]) = b4;
        __syncthreads();
#pragma unroll
        for (int k = 0; k < BK; k++) {
            float ra[TM], rb[TN];
#pragma unroll
            for (int i = 0; i < TM; i++) ra[i] = As[k][tr + i];
#pragma unroll
            for (int j = 0; j < TN; j++) rb[j] = Bs[k][tc + j];
#pragma unroll
            for (int i = 0; i < TM; i++)
#pragma unroll
                for (int j = 0; j < TN; j++) acc[i][j] = fmaf(ra[i], rb[j], acc[i][j]);
        }
        __syncthreads();
    }
#pragma unroll
    for (int i = 0; i < TM; i++) {
        int gr = br + tr + i;
        if (gr < M) {
#pragma unroll
            for (int j = 0; j < TN; j += 4) {
                float4 v = make_float4(acc[i][j], acc[i][j + 1], acc[i][j + 2], acc[i][j + 3]);
                *reinterpret_cast<float4*>(&C[(size_t)gr * N + bc + tc + j]) = v;
            }
        }
    }
}

// ---------------- edge pass 1: score + segment max ----------------
__global__ void k_edge_score(const void* __restrict__ ei,
                             const float* __restrict__ att, int E, int N) {
    int warp = (blockIdx.x * blockDim.x + threadIdx.x) >> 5;
    int lane = threadIdx.x & 31;
    int et = E + N;
    if (warp >= et) return;
    int src, dst;
    if (warp < E) {
        src = load_idx(ei, warp);
        dst = load_idx(ei, E + warp);
    } else {
        src = dst = warp - E;
    }
    const float* xls = g_xl + (size_t)src * HC;
    const float* xrd = g_xr + (size_t)dst * HC;
#pragma unroll
    for (int h = 0; h < 4; h++) {
        int c0 = h * 64 + lane;
        float s0 = xls[c0] + xrd[c0];
        float s1 = xls[c0 + 32] + xrd[c0 + 32];
        s0 = s0 > 0.f ? s0 : 0.2f * s0;
        s1 = s1 > 0.f ? s1 : 0.2f * s1;
        float p = __ldg(&att[h * 64 + lane]) * s0 + __ldg(&att[h * 64 + lane + 32]) * s1;
#pragma unroll
        for (int o = 16; o; o >>= 1) p += __shfl_xor_sync(0xFFFFFFFFu, p, o);
        if (lane == 0) {
            g_score[warp * 4 + h] = p;
            atomicMax(&g_smax[dst * 4 + h], f2o(p));
        }
    }
}

// ---------------- edge pass 2: exp + segment sum ----------------
__global__ void k_edge_exp(const void* __restrict__ ei, int E, int N) {
    int t = blockIdx.x * blockDim.x + threadIdx.x;
    int total = (E + N) * 4;
    if (t >= total) return;
    int e = t >> 2, h = t & 3;
    int dst = (e < E) ? load_idx(ei, E + e) : (e - E);
    float m = o2f(g_smax[dst * 4 + h]);
    float v = __expf(g_score[t] - m);
    g_score[t] = v;
    atomicAdd(&g_denom[dst * 4 + h], v);
}

// ---------------- edge pass 3: weighted scatter aggregate ----------------
__global__ void k_edge_agg(const void* __restrict__ ei, int E, int N) {
    int warp = (blockIdx.x * blockDim.x + threadIdx.x) >> 5;
    int lane = threadIdx.x & 31;
    int et = E + N;
    if (warp >= et) return;
    int src, dst;
    if (warp < E) {
        src = load_idx(ei, warp);
        dst = load_idx(ei, E + warp);
    } else {
        src = dst = warp - E;
    }
    const float* xls = g_xl + (size_t)src * HC;
    float* od = g_agg + (size_t)dst * HC;
#pragma unroll
    for (int h = 0; h < 4; h++) {
        float alpha = g_score[warp * 4 + h] / g_denom[dst * 4 + h];
        atomicAdd(&od[h * 64 + lane], alpha * xls[h * 64 + lane]);
        atomicAdd(&od[h * 64 + lane + 32], alpha * xls[h * 64 + lane + 32]);
    }
}

// ---------------- relu(agg + bias) -> h ----------------
__global__ void k_relu_bias(const float* __restrict__ b, int n) {
    int i = blockIdx.x * blockDim.x + threadIdx.x;
    if (i < n * HC) {
        float v = g_agg[i] + b[i & (HC - 1)];
        g_h[i] = v > 0.f ? v : 0.f;
    }
}

// ---------------- layer2 epilogue: relu(agg + bias), column-sum into g_gvec ----------------
__global__ void k_relu_bias_mean(const float* __restrict__ b, int n) {
    int col = threadIdx.x;  // 256 threads
    float bias = b[col];
    float acc = 0.f;
    for (int r = blockIdx.x; r < n; r += gridDim.x) {
        float v = g_agg[(size_t)r * HC + col] + bias;
        acc += v > 0.f ? v : 0.f;
    }
    atomicAdd(&g_gvec[col], acc);
}

// ---------------- final FC: out = (gvec/n) @ Wfc + bfc ----------------
__global__ void k_fc(const float* __restrict__ Wfc, const float* __restrict__ bfc,
                     float* __restrict__ out, int n) {
    int lane = threadIdx.x & 31;
    int w = threadIdx.x >> 5;  // 2 warps -> 2 outputs
    if (w >= 2) return;
    float acc = 0.f;
    for (int c = lane; c < HC; c += 32) acc += g_gvec[c] * Wfc[c * 2 + w];
#pragma unroll
    for (int o = 16; o; o >>= 1) acc += __shfl_xor_sync(0xFFFFFFFFu, acc, o);
    if (lane == 0) out[w] = acc / (float)n + bfc[w];
}

// ---------------- launch ----------------
extern "C" void kernel_launch(void* const* d_in, const int* in_sizes, int n_in,
                              void* d_out, int out_size) {
    const float* x        = (const float*)d_in[0];
    const void*  ei       = d_in[1];
    const float* Wl1      = (const float*)d_in[2];
    const float* Wr1      = (const float*)d_in[3];
    const float* att1     = (const float*)d_in[4];
    const float* b1       = (const float*)d_in[5];
    const float* Wl2      = (const float*)d_in[6];
    const float* Wr2      = (const float*)d_in[7];
    const float* att2     = (const float*)d_in[8];
    const float* b2       = (const float*)d_in[9];
    const float* Wfc      = (const float*)d_in[10];
    const float* bfc      = (const float*)d_in[11];
    float* out            = (float*)d_out;

    int n = in_sizes[0] / HC;   // 20000
    int e = in_sizes[1] / 2;    // 320000
    int et = e + n;

    float *p_xl, *p_xr, *p_h;
    cudaGetSymbolAddress((void**)&p_xl, g_xl);
    cudaGetSymbolAddress((void**)&p_xr, g_xr);
    cudaGetSymbolAddress((void**)&p_h, g_h);

    dim3 gGemm(2, (n + 127) / 128);
    int bInit = (n * 4 + 255) / 256;
    int bEdgeWarp = (et * 32 + 255) / 256;
    int bEdgeThr = (et * 4 + 255) / 256;
    int bElem = (n * HC + 255) / 256;

    // ---- dtype probe for edge_index ----
    k_detect<<<1, 32>>>((const int*)ei);

    // ---- layer 1 ----
    k_init<<<bInit, 256>>>(n);
    k_sgemm<<<gGemm, 256>>>(x, Wl1, p_xl, n);
    k_sgemm<<<gGemm, 256>>>(x, Wr1, p_xr, n);
    k_edge_score<<<bEdgeWarp, 256>>>(ei, att1, e, n);
    k_edge_exp<<<bEdgeThr, 256>>>(ei, e, n);
    k_edge_agg<<<bEdgeWarp, 256>>>(ei, e, n);
    k_relu_bias<<<bElem, 256>>>(b1, n);

    // ---- layer 2 ----
    k_init<<<bInit, 256>>>(n);
    k_sgemm<<<gGemm, 256>>>(p_h, Wl2, p_xl, n);
    k_sgemm<<<gGemm, 256>>>(p_h, Wr2, p_xr, n);
    k_edge_score<<<bEdgeWarp, 256>>>(ei, att2, e, n);
    k_edge_exp<<<bEdgeThr, 256>>>(ei, e, n);
    k_edge_agg<<<bEdgeWarp, 256>>>(ei, e, n);

    // ---- readout ----
    k_relu_bias_mean<<<256, 256>>>(b2, n);
    k_fc<<<1, 64>>>(Wfc, bfc, out, n);
}

// round 4
// speedup vs baseline: 1.3951x; 1.3951x over previous
#include <cuda_runtime.h>
#include <cuda_bf16.h>
#include <climits>
#include <cstdint>

#define NN 20000
#define EE 320000
#define ET (EE + NN)
#define HC 256

// ---------------- scratch ----------------
__device__ float g_xl[NN * HC];
__device__ float g_xr[NN * HC];
__device__ float g_h[NN * HC];     // layer1 output / layer2 input
__device__ float g_o2[NN * HC];    // layer2 output
__device__ float g_score[ET * 4];  // exp(score) per edge per head
__device__ int   g_cnt[NN];
__device__ int   g_off[NN + 1];
__device__ int   g_cur[NN];
__device__ int   g_csr_src[ET];
__device__ int   g_csr_eid[ET];
__device__ float g_gvec[HC];
__device__ int   g_is64;

// edge_index may be int32 (JAX x64 disabled) or int64
__device__ __forceinline__ int load_idx(const void* ei, int pos) {
    if (g_is64) return (int)((const long long*)ei)[pos];
    return ((const int*)ei)[pos];
}

// ---------------- dtype probe ----------------
__global__ void k_detect(const int* __restrict__ ei32) {
    int lane = threadIdx.x;
    int nz = 0;
    for (int i = lane * 2 + 1; i < 4096; i += 64) nz |= (ei32[i] != 0);
#pragma unroll
    for (int o = 16; o; o >>= 1) nz |= __shfl_xor_sync(0xFFFFFFFFu, nz, o);
    if (lane == 0) g_is64 = nz ? 0 : 1;
}

// ---------------- zero counts + gvec ----------------
__global__ void k_zero(int n) {
    int i = blockIdx.x * blockDim.x + threadIdx.x;
    if (i < n) g_cnt[i] = 0;
    if (i < HC) g_gvec[i] = 0.f;
}

// ---------------- CSR: count in-degree (real edges only) ----------------
__global__ void k_count(const void* __restrict__ ei, int E) {
    int t = blockIdx.x * blockDim.x + threadIdx.x;
    if (t < E) atomicAdd(&g_cnt[load_idx(ei, E + t)], 1);
}

// ---------------- CSR: exclusive scan of (cnt+1) over n nodes, 1 block ----------------
__global__ void k_scan(int n) {
    __shared__ int sm[1024];
    int t = threadIdx.x;
    int chunk = (n + 1023) >> 10;
    int lo = t * chunk;
    int hi = min(lo + chunk, n);
    int s = 0;
    for (int i = lo; i < hi; i++) s += g_cnt[i] + 1;
    sm[t] = s;
    __syncthreads();
    for (int off = 1; off < 1024; off <<= 1) {
        int v = (t >= off) ? sm[t - off] : 0;
        __syncthreads();
        sm[t] += v;
        __syncthreads();
    }
    int run = sm[t] - s;  // exclusive prefix
    for (int i = lo; i < hi; i++) {
        g_off[i] = run;
        g_cur[i] = run;
        run += g_cnt[i] + 1;
    }
    if (t == 1023) g_off[n] = run;
}

// ---------------- CSR: fill (edges + self loops) ----------------
__global__ void k_fill(const void* __restrict__ ei, int E, int N) {
    int t = blockIdx.x * blockDim.x + threadIdx.x;
    int et = E + N;
    if (t >= et) return;
    int src, dst;
    if (t < E) {
        src = load_idx(ei, t);
        dst = load_idx(ei, E + t);
    } else {
        src = dst = t - E;
    }
    int pos = atomicAdd(&g_cur[dst], 1);
    g_csr_src[pos] = src;
    g_csr_eid[pos] = t;
}

// ---------------- SGEMM: paired launch (blockIdx.z selects B/C) ----------------
__global__ __launch_bounds__(256) void k_sgemm2(const float* __restrict__ A,
                                                const float* __restrict__ B0,
                                                const float* __restrict__ B1,
                                                float* __restrict__ C0,
                                                float* __restrict__ C1, int M) {
    constexpr int BM = 128, BN = 128, BK = 8, TM = 8, TN = 8;
    constexpr int K = 256, N = 256;
    const float* B = blockIdx.z ? B1 : B0;
    float* C = blockIdx.z ? C1 : C0;
    __shared__ float As[BK][BM];
    __shared__ float Bs[BK][BN];
    const int tid = threadIdx.x;
    const int br = blockIdx.y * BM;
    const int bc = blockIdx.x * BN;
    const int tr = (tid / 16) * TM;
    const int tc = (tid % 16) * TN;
    const int arow = tid >> 1;
    const int acol = (tid & 1) * 4;
    const int brow = tid >> 5;
    const int bcol = (tid & 31) * 4;

    float acc[TM][TN];
#pragma unroll
    for (int i = 0; i < TM; i++)
#pragma unroll
        for (int j = 0; j < TN; j++) acc[i][j] = 0.f;

    for (int k0 = 0; k0 < K; k0 += BK) {
        float4 a4 = make_float4(0.f, 0.f, 0.f, 0.f);
        int gr = br + arow;
        if (gr < M)
            a4 = *reinterpret_cast<const float4*>(&A[(size_t)gr * K + k0 + acol]);
        As[acol + 0][arow] = a4.x;
        As[acol + 1][arow] = a4.y;
        As[acol + 2][arow] = a4.z;
        As[acol + 3][arow] = a4.w;
        float4 b4 = *reinterpret_cast<const float4*>(&B[(size_t)(k0 + brow) * N + bc + bcol]);
        *reinterpret_cast<float4*>(&Bs[brow][bcol]) = b4;
        __syncthreads();
#pragma unroll
        for (int k = 0; k < BK; k++) {
            float ra[TM], rb[TN];
#pragma unroll
            for (int i = 0; i < TM; i++) ra[i] = As[k][tr + i];
#pragma unroll
            for (int j = 0; j < TN; j++) rb[j] = Bs[k][tc + j];
#pragma unroll
            for (int i = 0; i < TM; i++)
#pragma unroll
                for (int j = 0; j < TN; j++) acc[i][j] = fmaf(ra[i], rb[j], acc[i][j]);
        }
        __syncthreads();
    }
#pragma unroll
    for (int i = 0; i < TM; i++) {
        int gr = br + tr + i;
        if (gr < M) {
#pragma unroll
            for (int j = 0; j < TN; j += 4) {
                float4 v = make_float4(acc[i][j], acc[i][j + 1], acc[i][j + 2], acc[i][j + 3]);
                *reinterpret_cast<float4*>(&C[(size_t)gr * N + bc + tc + j]) = v;
            }
        }
    }
}

// ---------------- score pass: exp(att . leakyrelu(xl[src]+xr[dst])) per head ----------------
__global__ void k_score(const void* __restrict__ ei,
                        const float* __restrict__ att, int E, int N) {
    int warp = (blockIdx.x * blockDim.x + threadIdx.x) >> 5;
    int lane = threadIdx.x & 31;
    int et = E + N;
    if (warp >= et) return;
    int src, dst;
    if (warp < E) {
        src = load_idx(ei, warp);
        dst = load_idx(ei, E + warp);
    } else {
        src = dst = warp - E;
    }
    const float* xls = g_xl + (size_t)src * HC;
    const float* xrd = g_xr + (size_t)dst * HC;
    float pv[4];
#pragma unroll
    for (int h = 0; h < 4; h++) {
        int c0 = h * 64 + lane;
        float s0 = xls[c0] + xrd[c0];
        float s1 = xls[c0 + 32] + xrd[c0 + 32];
        s0 = s0 > 0.f ? s0 : 0.2f * s0;
        s1 = s1 > 0.f ? s1 : 0.2f * s1;
        float p = __ldg(&att[h * 64 + lane]) * s0 + __ldg(&att[h * 64 + lane + 32]) * s1;
#pragma unroll
        for (int o = 16; o; o >>= 1) p += __shfl_xor_sync(0xFFFFFFFFu, p, o);
        pv[h] = p;
    }
    if (lane == 0) {
        float4 ev = make_float4(__expf(pv[0]), __expf(pv[1]), __expf(pv[2]), __expf(pv[3]));
        *reinterpret_cast<float4*>(&g_score[(size_t)warp * 4]) = ev;
    }
}

// ---------------- gather: per-dst softmax-weighted aggregate + bias + relu ----------------
__global__ void k_gather(const float* __restrict__ bias, float* __restrict__ outp, int n) {
    int warp = (blockIdx.x * blockDim.x + threadIdx.x) >> 5;
    int lane = threadIdx.x & 31;
    if (warp >= n) return;
    int beg = g_off[warp];
    int end = g_off[warp + 1];
    int hi = lane >> 4;  // 0 or 1
    float4 a0 = make_float4(0.f, 0.f, 0.f, 0.f);
    float4 a1 = make_float4(0.f, 0.f, 0.f, 0.f);
    float d0 = 0.f, d1 = 0.f;
    const float4* XL = reinterpret_cast<const float4*>(g_xl);
    for (int e = beg; e < end; e++) {
        int src = g_csr_src[e];
        int eid = g_csr_eid[e];
        float4 sv = *reinterpret_cast<const float4*>(&g_score[(size_t)eid * 4]);
        float s0 = hi ? sv.y : sv.x;  // head of floats [lane*4 .. lane*4+3]
        float s1 = hi ? sv.w : sv.z;  // head of floats [128+lane*4 ..]
        float4 v0 = XL[(size_t)src * 64 + lane];
        float4 v1 = XL[(size_t)src * 64 + 32 + lane];
        a0.x += s0 * v0.x; a0.y += s0 * v0.y; a0.z += s0 * v0.z; a0.w += s0 * v0.w;
        a1.x += s1 * v1.x; a1.y += s1 * v1.y; a1.z += s1 * v1.z; a1.w += s1 * v1.w;
        d0 += s0;
        d1 += s1;
    }
    float i0 = 1.f / d0, i1 = 1.f / d1;
    const float4* B4 = reinterpret_cast<const float4*>(bias);
    float4 b0 = B4[lane], b1 = B4[32 + lane];
    float4 o0, o1;
    o0.x = fmaxf(a0.x * i0 + b0.x, 0.f);
    o0.y = fmaxf(a0.y * i0 + b0.y, 0.f);
    o0.z = fmaxf(a0.z * i0 + b0.z, 0.f);
    o0.w = fmaxf(a0.w * i0 + b0.w, 0.f);
    o1.x = fmaxf(a1.x * i1 + b1.x, 0.f);
    o1.y = fmaxf(a1.y * i1 + b1.y, 0.f);
    o1.z = fmaxf(a1.z * i1 + b1.z, 0.f);
    o1.w = fmaxf(a1.w * i1 + b1.w, 0.f);
    float4* O = reinterpret_cast<float4*>(outp);
    O[(size_t)warp * 64 + lane] = o0;
    O[(size_t)warp * 64 + 32 + lane] = o1;
}

// ---------------- column sums of layer-2 output ----------------
__global__ void k_mean(const float* __restrict__ src, int n) {
    int col = threadIdx.x;  // 256
    float acc = 0.f;
    for (int r = blockIdx.x; r < n; r += gridDim.x)
        acc += src[(size_t)r * HC + col];
    atomicAdd(&g_gvec[col], acc);
}

// ---------------- final FC ----------------
__global__ void k_fc(const float* __restrict__ Wfc, const float* __restrict__ bfc,
                     float* __restrict__ out, int n) {
    int lane = threadIdx.x & 31;
    int w = threadIdx.x >> 5;
    if (w >= 2) return;
    float acc = 0.f;
    for (int c = lane; c < HC; c += 32) acc += g_gvec[c] * Wfc[c * 2 + w];
#pragma unroll
    for (int o = 16; o; o >>= 1) acc += __shfl_xor_sync(0xFFFFFFFFu, acc, o);
    if (lane == 0) out[w] = acc / (float)n + bfc[w];
}

// ---------------- launch ----------------
extern "C" void kernel_launch(void* const* d_in, const int* in_sizes, int n_in,
                              void* d_out, int out_size) {
    const float* x   = (const float*)d_in[0];
    const void*  ei  = d_in[1];
    const float* Wl1 = (const float*)d_in[2];
    const float* Wr1 = (const float*)d_in[3];
    const float* att1= (const float*)d_in[4];
    const float* b1  = (const float*)d_in[5];
    const float* Wl2 = (const float*)d_in[6];
    const float* Wr2 = (const float*)d_in[7];
    const float* att2= (const float*)d_in[8];
    const float* b2  = (const float*)d_in[9];
    const float* Wfc = (const float*)d_in[10];
    const float* bfc = (const float*)d_in[11];
    float* out       = (float*)d_out;

    int n = in_sizes[0] / HC;  // 20000
    int e = in_sizes[1] / 2;   // 320000
    int et = e + n;

    float *p_xl, *p_xr, *p_h, *p_o2;
    cudaGetSymbolAddress((void**)&p_xl, g_xl);
    cudaGetSymbolAddress((void**)&p_xr, g_xr);
    cudaGetSymbolAddress((void**)&p_h, g_h);
    cudaGetSymbolAddress((void**)&p_o2, g_o2);

    dim3 gGemm(2, (n + 127) / 128, 2);
    int bEdgeWarp = (et * 32 + 255) / 256;
    int bNodeWarp = (n * 32 + 255) / 256;

    // ---- setup: dtype probe + CSR build (reused by both layers) ----
    k_detect<<<1, 32>>>((const int*)ei);
    k_zero<<<(n + 255) / 256, 256>>>(n);
    k_count<<<(e + 255) / 256, 256>>>(ei, e);
    k_scan<<<1, 1024>>>(n);
    k_fill<<<(et + 255) / 256, 256>>>(ei, e, n);

    // ---- layer 1 ----
    k_sgemm2<<<gGemm, 256>>>(x, Wl1, Wr1, p_xl, p_xr, n);
    k_score<<<bEdgeWarp, 256>>>(ei, att1, e, n);
    k_gather<<<bNodeWarp, 256>>>(b1, p_h, n);

    // ---- layer 2 ----
    k_sgemm2<<<gGemm, 256>>>(p_h, Wl2, Wr2, p_xl, p_xr, n);
    k_score<<<bEdgeWarp, 256>>>(ei, att2, e, n);
    k_gather<<<bNodeWarp, 256>>>(b2, p_o2, n);

    // ---- readout ----
    k_mean<<<256, 256>>>(p_o2, n);
    k_fc<<<1, 64>>>(Wfc, bfc, out, n);
}

// round 6
// speedup vs baseline: 1.4888x; 1.0672x over previous
#include <cuda_runtime.h>
#include <cuda_bf16.h>
#include <cstdint>

#define NN 20000
#define EE 320000
#define ET (EE + NN)
#define HC 256
#define KP 768          // extended K (hi*hi + hi*lo + lo*hi)

// ---------------- scratch ----------------
__device__ float g_xl[NN * HC];
__device__ float g_xr[NN * HC];
__device__ float g_h[NN * HC];
__device__ float g_o2[NN * HC];
__device__ float g_score[ET * 4];
__device__ int   g_cnt[NN];
__device__ int   g_off[NN + 1];
__device__ int   g_cur[NN];
__device__ int   g_csr_src[ET];
__device__ int   g_csr_eid[ET];
__device__ float g_gvec[HC];
__device__ int   g_is64;
__device__ int   g_part[128];
__device__ __nv_bfloat16 g_wt[4 * 256 * KP];   // W' per slot: [N=256][K'=768] = [Whi|Wlo|Whi]
__device__ __nv_bfloat16 g_ap[NN * 512];       // A' : [M][512] = [Ahi|Alo]

__device__ __forceinline__ uint32_t smem_u32(const void* p) {
    uint32_t a;
    asm("{ .reg .u64 t; cvta.to.shared.u64 t, %1; cvt.u32.u64 %0, t; }" : "=r"(a) : "l"(p));
    return a;
}
#define SMEM_SWZ(o) ((o) ^ (((o) >> 3) & 0x70))

// ---------------- index dtype handling ----------------
__device__ __forceinline__ int load_idx(const void* ei, int pos) {
    if (g_is64) return (int)((const long long*)ei)[pos];
    return ((const int*)ei)[pos];
}
__global__ void k_detect(const int* __restrict__ ei32) {
    int lane = threadIdx.x;
    int nz = 0;
    for (int i = lane * 2 + 1; i < 4096; i += 64) nz |= (ei32[i] != 0);
#pragma unroll
    for (int o = 16; o; o >>= 1) nz |= __shfl_xor_sync(0xFFFFFFFFu, nz, o);
    if (lane == 0) g_is64 = nz ? 0 : 1;
}

// ---------------- CSR build ----------------
__global__ void k_zero(int n) {
    int i = blockIdx.x * blockDim.x + threadIdx.x;
    if (i < n) g_cnt[i] = 0;
    if (i < HC) g_gvec[i] = 0.f;
}
__global__ void k_count(const void* __restrict__ ei, int E) {
    int t = blockIdx.x * blockDim.x + threadIdx.x;
    if (t < E) atomicAdd(&g_cnt[load_idx(ei, E + t)], 1);
}
__global__ void k_scanA(int n) {
    __shared__ int sm[256];
    int i = blockIdx.x * 256 + threadIdx.x;
    int v = (i < n) ? g_cnt[i] + 1 : 0;
    sm[threadIdx.x] = v;
    __syncthreads();
    for (int o = 128; o; o >>= 1) {
        if (threadIdx.x < o) sm[threadIdx.x] += sm[threadIdx.x + o];
        __syncthreads();
    }
    if (threadIdx.x == 0) g_part[blockIdx.x] = sm[0];
}
__global__ void k_scanB(int nb) {
    if (threadIdx.x == 0) {
        int run = 0;
        for (int b = 0; b < nb; b++) { int v = g_part[b]; g_part[b] = run; run += v; }
    }
}
__global__ void k_scanC(int n) {
    __shared__ int sm[256];
    int i = blockIdx.x * 256 + threadIdx.x;
    int v = (i < n) ? g_cnt[i] + 1 : 0;
    sm[threadIdx.x] = v;
    __syncthreads();
    for (int o = 1; o < 256; o <<= 1) {
        int t = (threadIdx.x >= o) ? sm[threadIdx.x - o] : 0;
        __syncthreads();
        sm[threadIdx.x] += t;
        __syncthreads();
    }
    int excl = sm[threadIdx.x] - v + g_part[blockIdx.x];
    if (i < n) {
        g_off[i] = excl;
        g_cur[i] = excl;
        if (i == n - 1) g_off[n] = excl + v;
    }
}
__global__ void k_fill(const void* __restrict__ ei, int E, int N) {
    int t = blockIdx.x * blockDim.x + threadIdx.x;
    int et = E + N;
    if (t >= et) return;
    int src, dst;
    if (t < E) { src = load_idx(ei, t); dst = load_idx(ei, E + t); }
    else       { src = dst = t - E; }
    int pos = atomicAdd(&g_cur[dst], 1);
    g_csr_src[pos] = src;
    g_csr_eid[pos] = t;
}

// ---------------- weight transpose + split: W' [slot][N][768] = [Whi|Wlo|Whi] ----------------
__global__ void k_wsplit(const float* __restrict__ W0, const float* __restrict__ W1,
                         const float* __restrict__ W2, const float* __restrict__ W3) {
    __shared__ float t[32][33];
    const float* W = blockIdx.z == 0 ? W0 : blockIdx.z == 1 ? W1 : blockIdx.z == 2 ? W2 : W3;
    int k0 = blockIdx.x * 32, j0 = blockIdx.y * 32;
    int tx = threadIdx.x, ty = threadIdx.y;  // (32, 8)
#pragma unroll
    for (int r = 0; r < 32; r += 8) t[ty + r][tx] = W[(size_t)(k0 + ty + r) * 256 + j0 + tx];
    __syncthreads();
    size_t base = (size_t)blockIdx.z * 256 * KP;
#pragma unroll
    for (int r = 0; r < 32; r += 8) {
        float v = t[tx][ty + r];
        __nv_bfloat16 hi = __float2bfloat16(v);
        __nv_bfloat16 lo = __float2bfloat16(v - __bfloat162float(hi));
        size_t row = base + (size_t)(j0 + ty + r) * KP;
        g_wt[row + k0 + tx] = hi;
        g_wt[row + 256 + k0 + tx] = lo;
        g_wt[row + 512 + k0 + tx] = hi;
    }
}

// ---------------- A split: A'[M][512] = [Ahi|Alo] ----------------
__global__ void k_asplit(const float* __restrict__ A, int M) {
    int t = blockIdx.x * blockDim.x + threadIdx.x;
    int total = M * 64;  // float4 granules
    if (t >= total) return;
    int row = t >> 6, k = (t & 63) * 4;
    float4 a = *reinterpret_cast<const float4*>(&A[(size_t)row * 256 + k]);
    __nv_bfloat16 hx = __float2bfloat16(a.x), hy = __float2bfloat16(a.y);
    __nv_bfloat16 hz = __float2bfloat16(a.z), hw = __float2bfloat16(a.w);
    __nv_bfloat16 lx = __float2bfloat16(a.x - __bfloat162float(hx));
    __nv_bfloat16 ly = __float2bfloat16(a.y - __bfloat162float(hy));
    __nv_bfloat16 lz = __float2bfloat16(a.z - __bfloat162float(hz));
    __nv_bfloat16 lw = __float2bfloat16(a.w - __bfloat162float(hw));
    __nv_bfloat162 h01 = __halves2bfloat162(hx, hy), h23 = __halves2bfloat162(hz, hw);
    __nv_bfloat162 l01 = __halves2bfloat162(lx, ly), l23 = __halves2bfloat162(lz, lw);
    uint2* dh = reinterpret_cast<uint2*>(&g_ap[(size_t)row * 512 + k]);
    uint2* dl = reinterpret_cast<uint2*>(&g_ap[(size_t)row * 512 + 256 + k]);
    *dh = make_uint2(*(uint32_t*)&h01, *(uint32_t*)&h23);
    *dl = make_uint2(*(uint32_t*)&l01, *(uint32_t*)&l23);
}

// ---------------- HMMA GEMM: C[M,256] = A'[M,768'] @ W'[N,768]^T ----------------
// grid: (ceil(M/128), 2 n-tiles, 2 weights). 256 thr, 8 warps (2 m x 4 n), warp tile 64x32.
#define NCHUNK 12
__global__ __launch_bounds__(256) void k_mma(int wbase, float* __restrict__ C0,
                                             float* __restrict__ C1, int M) {
    extern __shared__ char smem[];
    const uint32_t sb = smem_u32(smem);
    const int tid = threadIdx.x, lane = tid & 31, wid = tid >> 5;
    const int warpM = wid >> 2, warpN = wid & 3;
    const int br = blockIdx.x * 128;
    const int ybase = blockIdx.y * 128;
    const __nv_bfloat16* Bp = g_wt + ((size_t)(wbase + blockIdx.z) * 256 + ybase) * KP;
    float* C = blockIdx.z ? C1 : C0;

    float acc[4][4][4];
#pragma unroll
    for (int i = 0; i < 4; i++)
#pragma unroll
        for (int j = 0; j < 4; j++)
#pragma unroll
            for (int q = 0; q < 4; q++) acc[i][j][q] = 0.f;

    // chunk loader: A' 128x64 + B 128x64 bf16 into swizzled smem stage
    auto load_chunk = [&](int c, int stage) {
        int aoff = (c < 4) ? c * 64 : (c < 8) ? (c - 4) * 64 : 256 + (c - 8) * 64;
        int boff = c * 64;
        uint32_t sA = sb + stage * 32768;
        uint32_t sB = sA + 16384;
#pragma unroll
        for (int i = 0; i < 4; i++) {
            int idx = tid + i * 256;          // 0..1023
            int row = idx >> 3;
            int cb = (idx & 7) * 16;
            int ar = br + row;
            if (ar >= M) ar = M - 1;
            const char* srcA = (const char*)(g_ap + (size_t)ar * 512 + aoff) + cb;
            uint32_t dA = sA + SMEM_SWZ(row * 128 + cb);
            asm volatile("cp.async.cg.shared.global [%0], [%1], 16;" :: "r"(dA), "l"(srcA));
            const char* srcB = (const char*)(Bp + (size_t)row * KP + boff) + cb;
            uint32_t dB = sB + SMEM_SWZ(row * 128 + cb);
            asm volatile("cp.async.cg.shared.global [%0], [%1], 16;" :: "r"(dB), "l"(srcB));
        }
    };

    load_chunk(0, 0);
    asm volatile("cp.async.commit_group;");

    const int alr = lane & 15, aks = lane >> 4;
    const int bro = (lane & 7) + ((lane >> 4) << 3);
    const int bko = ((lane >> 3) & 1) * 16;

    for (int c = 0; c < NCHUNK; c++) {
        if (c + 1 < NCHUNK) {
            load_chunk(c + 1, (c + 1) & 1);
            asm volatile("cp.async.commit_group;");
            asm volatile("cp.async.wait_group 1;");
        } else {
            asm volatile("cp.async.wait_group 0;");
        }
        __syncthreads();
        uint32_t sA = sb + (c & 1) * 32768;
        uint32_t sB = sA + 16384;
#pragma unroll
        for (int ks = 0; ks < 4; ks++) {
            int kb = ks * 32;
            uint32_t a[4][4], b[2][4];
#pragma unroll
            for (int mi = 0; mi < 4; mi++) {
                int row = warpM * 64 + mi * 16 + alr;
                uint32_t ad = sA + SMEM_SWZ(row * 128 + kb + aks * 16);
                asm volatile("ldmatrix.sync.aligned.m8n8.x4.shared.b16 {%0,%1,%2,%3}, [%4];"
                             : "=r"(a[mi][0]), "=r"(a[mi][1]), "=r"(a[mi][2]), "=r"(a[mi][3])
                             : "r"(ad));
            }
#pragma unroll
            for (int nj = 0; nj < 2; nj++) {
                int row = warpN * 32 + nj * 16 + bro;
                uint32_t bd = sB + SMEM_SWZ(row * 128 + kb + bko);
                asm volatile("ldmatrix.sync.aligned.m8n8.x4.shared.b16 {%0,%1,%2,%3}, [%4];"
                             : "=r"(b[nj][0]), "=r"(b[nj][1]), "=r"(b[nj][2]), "=r"(b[nj][3])
                             : "r"(bd));
            }
#pragma unroll
            for (int mi = 0; mi < 4; mi++)
#pragma unroll
                for (int n8 = 0; n8 < 4; n8++) {
                    uint32_t b0 = b[n8 >> 1][(n8 & 1) * 2];
                    uint32_t b1 = b[n8 >> 1][(n8 & 1) * 2 + 1];
                    asm volatile(
                        "mma.sync.aligned.m16n8k16.row.col.f32.bf16.bf16.f32 "
                        "{%0,%1,%2,%3}, {%4,%5,%6,%7}, {%8,%9}, {%0,%1,%2,%3};"
                        : "+f"(acc[mi][n8][0]), "+f"(acc[mi][n8][1]),
                          "+f"(acc[mi][n8][2]), "+f"(acc[mi][n8][3])
                        : "r"(a[mi][0]), "r"(a[mi][1]), "r"(a[mi][2]), "r"(a[mi][3]),
                          "r"(b0), "r"(b1));
                }
        }
        __syncthreads();
    }

    // epilogue
    int g = lane >> 2, c2 = (lane & 3) * 2;
#pragma unroll
    for (int mi = 0; mi < 4; mi++) {
        int r0 = br + warpM * 64 + mi * 16 + g;
#pragma unroll
        for (int n8 = 0; n8 < 4; n8++) {
            int col = ybase + warpN * 32 + n8 * 8 + c2;
            if (r0 < M) {
                C[(size_t)r0 * 256 + col] = acc[mi][n8][0];
                C[(size_t)r0 * 256 + col + 1] = acc[mi][n8][1];
            }
            if (r0 + 8 < M) {
                C[(size_t)(r0 + 8) * 256 + col] = acc[mi][n8][2];
                C[(size_t)(r0 + 8) * 256 + col + 1] = acc[mi][n8][3];
            }
        }
    }
}

// ---------------- score pass ----------------
__global__ void k_score(const void* __restrict__ ei,
                        const float* __restrict__ att, int E, int N) {
    int warp = (blockIdx.x * blockDim.x + threadIdx.x) >> 5;
    int lane = threadIdx.x & 31;
    int et = E + N;
    if (warp >= et) return;
    int src, dst;
    if (warp < E) { src = load_idx(ei, warp); dst = load_idx(ei, E + warp); }
    else          { src = dst = warp - E; }
    const float* xls = g_xl + (size_t)src * HC;
    const float* xrd = g_xr + (size_t)dst * HC;
    float pv[4];
#pragma unroll
    for (int h = 0; h < 4; h++) {
        int c0 = h * 64 + lane;
        float s0 = xls[c0] + xrd[c0];
        float s1 = xls[c0 + 32] + xrd[c0 + 32];
        s0 = s0 > 0.f ? s0 : 0.2f * s0;
        s1 = s1 > 0.f ? s1 : 0.2f * s1;
        float p = __ldg(&att[h * 64 + lane]) * s0 + __ldg(&att[h * 64 + lane + 32]) * s1;
#pragma unroll
        for (int o = 16; o; o >>= 1) p += __shfl_xor_sync(0xFFFFFFFFu, p, o);
        pv[h] = p;
    }
    if (lane == 0) {
        float4 ev = make_float4(__expf(pv[0]), __expf(pv[1]), __expf(pv[2]), __expf(pv[3]));
        *reinterpret_cast<float4*>(&g_score[(size_t)warp * 4]) = ev;
    }
}

// ---------------- gather ----------------
__global__ void k_gather(const float* __restrict__ bias, float* __restrict__ outp, int n) {
    int warp = (blockIdx.x * blockDim.x + threadIdx.x) >> 5;
    int lane = threadIdx.x & 31;
    if (warp >= n) return;
    int beg = g_off[warp];
    int end = g_off[warp + 1];
    int hi = lane >> 4;
    float4 a0 = make_float4(0.f, 0.f, 0.f, 0.f);
    float4 a1 = make_float4(0.f, 0.f, 0.f, 0.f);
    float d0 = 0.f, d1 = 0.f;
    const float4* XL = reinterpret_cast<const float4*>(g_xl);
    for (int e = beg; e < end; e++) {
        int src = g_csr_src[e];
        int eid = g_csr_eid[e];
        float4 sv = *reinterpret_cast<const float4*>(&g_score[(size_t)eid * 4]);
        float s0 = hi ? sv.y : sv.x;
        float s1 = hi ? sv.w : sv.z;
        float4 v0 = XL[(size_t)src * 64 + lane];
        float4 v1 = XL[(size_t)src * 64 + 32 + lane];
        a0.x += s0 * v0.x; a0.y += s0 * v0.y; a0.z += s0 * v0.z; a0.w += s0 * v0.w;
        a1.x += s1 * v1.x; a1.y += s1 * v1.y; a1.z += s1 * v1.z; a1.w += s1 * v1.w;
        d0 += s0;
        d1 += s1;
    }
    float i0 = 1.f / d0, i1 = 1.f / d1;
    const float4* B4 = reinterpret_cast<const float4*>(bias);
    float4 b0 = B4[lane], b1 = B4[32 + lane];
    float4 o0, o1;
    o0.x = fmaxf(a0.x * i0 + b0.x, 0.f); o0.y = fmaxf(a0.y * i0 + b0.y, 0.f);
    o0.z = fmaxf(a0.z * i0 + b0.z, 0.f); o0.w = fmaxf(a0.w * i0 + b0.w, 0.f);
    o1.x = fmaxf(a1.x * i1 + b1.x, 0.f); o1.y = fmaxf(a1.y * i1 + b1.y, 0.f);
    o1.z = fmaxf(a1.z * i1 + b1.z, 0.f); o1.w = fmaxf(a1.w * i1 + b1.w, 0.f);
    float4* O = reinterpret_cast<float4*>(outp);
    O[(size_t)warp * 64 + lane] = o0;
    O[(size_t)warp * 64 + 32 + lane] = o1;
}

// ---------------- readout ----------------
__global__ void k_mean(const float* __restrict__ src, int n) {
    int col = threadIdx.x;
    float acc = 0.f;
    for (int r = blockIdx.x; r < n; r += gridDim.x)
        acc += src[(size_t)r * HC + col];
    atomicAdd(&g_gvec[col], acc);
}
__global__ void k_fc(const float* __restrict__ Wfc, const float* __restrict__ bfc,
                     float* __restrict__ out, int n) {
    int lane = threadIdx.x & 31;
    int w = threadIdx.x >> 5;
    if (w >= 2) return;
    float acc = 0.f;
    for (int c = lane; c < HC; c += 32) acc += g_gvec[c] * Wfc[c * 2 + w];
#pragma unroll
    for (int o = 16; o; o >>= 1) acc += __shfl_xor_sync(0xFFFFFFFFu, acc, o);
    if (lane == 0) out[w] = acc / (float)n + bfc[w];
}

// ---------------- launch ----------------
extern "C" void kernel_launch(void* const* d_in, const int* in_sizes, int n_in,
                              void* d_out, int out_size) {
    const float* x   = (const float*)d_in[0];
    const void*  ei  = d_in[1];
    const float* Wl1 = (const float*)d_in[2];
    const float* Wr1 = (const float*)d_in[3];
    const float* att1= (const float*)d_in[4];
    const float* b1  = (const float*)d_in[5];
    const float* Wl2 = (const float*)d_in[6];
    const float* Wr2 = (const float*)d_in[7];
    const float* att2= (const float*)d_in[8];
    const float* b2  = (const float*)d_in[9];
    const float* Wfc = (const float*)d_in[10];
    const float* bfc = (const float*)d_in[11];
    float* out       = (float*)d_out;

    int n = in_sizes[0] / HC;  // 20000
    int e = in_sizes[1] / 2;   // 320000
    int et = e + n;
    int nb = (n + 255) / 256;

    float *p_xl, *p_xr, *p_h, *p_o2;
    cudaGetSymbolAddress((void**)&p_xl, g_xl);
    cudaGetSymbolAddress((void**)&p_xr, g_xr);
    cudaGetSymbolAddress((void**)&p_h, g_h);
    cudaGetSymbolAddress((void**)&p_o2, g_o2);

    cudaFuncSetAttribute(k_mma, cudaFuncAttributeMaxDynamicSharedMemorySize, 65536);

    dim3 gMma((n + 127) / 128, 2, 2);
    int bEdgeWarp = (et * 32 + 255) / 256;
    int bNodeWarp = (n * 32 + 255) / 256;
    int bSplit = (n * 64 + 255) / 256;

    // ---- setup ----
    k_detect<<<1, 32>>>((const int*)ei);
    k_wsplit<<<dim3(8, 8, 4), dim3(32, 8)>>>(Wl1, Wr1, Wl2, Wr2);
    k_zero<<<(n + 255) / 256, 256>>>(n);
    k_count<<<(e + 255) / 256, 256>>>(ei, e);
    k_scanA<<<nb, 256>>>(n);
    k_scanB<<<1, 32>>>(nb);
    k_scanC<<<nb, 256>>>(n);
    k_fill<<<(et + 255) / 256, 256>>>(ei, e, n);

    // ---- layer 1 ----
    k_asplit<<<bSplit, 256>>>(x, n);
    k_mma<<<gMma, 256, 65536>>>(0, p_xl, p_xr, n);
    k_score<<<bEdgeWarp, 256>>>(ei, att1, e, n);
    k_gather<<<bNodeWarp, 256>>>(b1, p_h, n);

    // ---- layer 2 ----
    k_asplit<<<bSplit, 256>>>(p_h, n);
    k_mma<<<gMma, 256, 65536>>>(2, p_xl, p_xr, n);
    k_score<<<bEdgeWarp, 256>>>(ei, att2, e, n);
    k_gather<<<bNodeWarp, 256>>>(b2, p_o2, n);

    // ---- readout ----
    k_mean<<<256, 256>>>(p_o2, n);
    k_fc<<<1, 64>>>(Wfc, bfc, out, n);
}

// round 7
// speedup vs baseline: 2.1210x; 1.4246x over previous
#include <cuda_runtime.h>
#include <cuda_bf16.h>
#include <cstdint>

#define NN 20000
#define EE 320000
#define ET (EE + NN)
#define HC 256
#define KP 768          // extended K (hi*hi + hi*lo + lo*hi)

// ---------------- scratch ----------------
__device__ float g_xl[NN * HC];
__device__ float g_xr[NN * HC];
__device__ float g_o2[NN * HC];
__device__ float g_score[ET * 4];
__device__ int   g_cnt[NN];
__device__ int   g_off[NN + 1];
__device__ int   g_cur[NN];
__device__ int   g_csr_src[ET];
__device__ int   g_csr_eid[ET];
__device__ float g_gvec[HC];
__device__ int   g_is64;
__device__ int   g_part[128];
__device__ __nv_bfloat16 g_wt[4 * 256 * KP];   // W' per slot: [N=256][K'=768] = [Whi|Wlo|Whi]
__device__ __nv_bfloat16 g_ap[NN * 512];       // A' : [M][512] = [Ahi|Alo]

__device__ __forceinline__ uint32_t smem_u32(const void* p) {
    uint32_t a;
    asm("{ .reg .u64 t; cvta.to.shared.u64 t, %1; cvt.u32.u64 %0, t; }" : "=r"(a) : "l"(p));
    return a;
}
#define SMEM_SWZ(o) ((o) ^ (((o) >> 3) & 0x70))

__device__ __forceinline__ void split4(float4 a, uint2& vh, uint2& vl) {
    __nv_bfloat16 hx = __float2bfloat16(a.x), hy = __float2bfloat16(a.y);
    __nv_bfloat16 hz = __float2bfloat16(a.z), hw = __float2bfloat16(a.w);
    __nv_bfloat16 lx = __float2bfloat16(a.x - __bfloat162float(hx));
    __nv_bfloat16 ly = __float2bfloat16(a.y - __bfloat162float(hy));
    __nv_bfloat16 lz = __float2bfloat16(a.z - __bfloat162float(hz));
    __nv_bfloat16 lw = __float2bfloat16(a.w - __bfloat162float(hw));
    __nv_bfloat162 h01 = __halves2bfloat162(hx, hy), h23 = __halves2bfloat162(hz, hw);
    __nv_bfloat162 l01 = __halves2bfloat162(lx, ly), l23 = __halves2bfloat162(lz, lw);
    vh = make_uint2(*(uint32_t*)&h01, *(uint32_t*)&h23);
    vl = make_uint2(*(uint32_t*)&l01, *(uint32_t*)&l23);
}

// ---------------- index dtype handling ----------------
__device__ __forceinline__ int load_idx(const void* ei, int pos) {
    if (g_is64) return (int)((const long long*)ei)[pos];
    return ((const int*)ei)[pos];
}
__global__ void k_detect(const int* __restrict__ ei32) {
    int lane = threadIdx.x;
    int nz = 0;
    for (int i = lane * 2 + 1; i < 4096; i += 64) nz |= (ei32[i] != 0);
#pragma unroll
    for (int o = 16; o; o >>= 1) nz |= __shfl_xor_sync(0xFFFFFFFFu, nz, o);
    if (lane == 0) g_is64 = nz ? 0 : 1;
}

// ---------------- CSR build ----------------
__global__ void k_zero(int n) {
    int i = blockIdx.x * blockDim.x + threadIdx.x;
    if (i < n) g_cnt[i] = 0;
    if (i < HC) g_gvec[i] = 0.f;
}
__global__ void k_count(const void* __restrict__ ei, int E) {
    int t = blockIdx.x * blockDim.x + threadIdx.x;
    if (t < E) atomicAdd(&g_cnt[load_idx(ei, E + t)], 1);
}
__global__ void k_scanA(int n) {
    __shared__ int sm[256];
    int i = blockIdx.x * 256 + threadIdx.x;
    int v = (i < n) ? g_cnt[i] + 1 : 0;
    sm[threadIdx.x] = v;
    __syncthreads();
    for (int o = 128; o; o >>= 1) {
        if (threadIdx.x < o) sm[threadIdx.x] += sm[threadIdx.x + o];
        __syncthreads();
    }
    if (threadIdx.x == 0) g_part[blockIdx.x] = sm[0];
}
__global__ void k_scanB(int nb) {
    if (threadIdx.x == 0) {
        int run = 0;
        for (int b = 0; b < nb; b++) { int v = g_part[b]; g_part[b] = run; run += v; }
    }
}
__global__ void k_scanC(int n) {
    __shared__ int sm[256];
    int i = blockIdx.x * 256 + threadIdx.x;
    int v = (i < n) ? g_cnt[i] + 1 : 0;
    sm[threadIdx.x] = v;
    __syncthreads();
    for (int o = 1; o < 256; o <<= 1) {
        int t = (threadIdx.x >= o) ? sm[threadIdx.x - o] : 0;
        __syncthreads();
        sm[threadIdx.x] += t;
        __syncthreads();
    }
    int excl = sm[threadIdx.x] - v + g_part[blockIdx.x];
    if (i < n) {
        g_off[i] = excl;
        g_cur[i] = excl;
        if (i == n - 1) g_off[n] = excl + v;
    }
}
__global__ void k_fill(const void* __restrict__ ei, int E, int N) {
    int t = blockIdx.x * blockDim.x + threadIdx.x;
    int et = E + N;
    if (t >= et) return;
    int src, dst;
    if (t < E) { src = load_idx(ei, t); dst = load_idx(ei, E + t); }
    else       { src = dst = t - E; }
    int pos = atomicAdd(&g_cur[dst], 1);
    g_csr_src[pos] = src;
    g_csr_eid[pos] = t;
}

// ---------------- weight transpose + split: W' [slot][N][768] = [Whi|Wlo|Whi] ----------------
__global__ void k_wsplit(const float* __restrict__ W0, const float* __restrict__ W1,
                         const float* __restrict__ W2, const float* __restrict__ W3) {
    __shared__ float t[32][33];
    const float* W = blockIdx.z == 0 ? W0 : blockIdx.z == 1 ? W1 : blockIdx.z == 2 ? W2 : W3;
    int k0 = blockIdx.x * 32, j0 = blockIdx.y * 32;
    int tx = threadIdx.x, ty = threadIdx.y;  // (32, 8)
#pragma unroll
    for (int r = 0; r < 32; r += 8) t[ty + r][tx] = W[(size_t)(k0 + ty + r) * 256 + j0 + tx];
    __syncthreads();
    size_t base = (size_t)blockIdx.z * 256 * KP;
#pragma unroll
    for (int r = 0; r < 32; r += 8) {
        float v = t[tx][ty + r];
        __nv_bfloat16 hi = __float2bfloat16(v);
        __nv_bfloat16 lo = __float2bfloat16(v - __bfloat162float(hi));
        size_t row = base + (size_t)(j0 + ty + r) * KP;
        g_wt[row + k0 + tx] = hi;
        g_wt[row + 256 + k0 + tx] = lo;
        g_wt[row + 512 + k0 + tx] = hi;
    }
}

// ---------------- A split (layer-1 input x only): A'[M][512] = [Ahi|Alo] ----------------
__global__ void k_asplit(const float* __restrict__ A, int M) {
    int t = blockIdx.x * blockDim.x + threadIdx.x;
    int total = M * 64;
    if (t >= total) return;
    int row = t >> 6, k = (t & 63) * 4;
    float4 a = *reinterpret_cast<const float4*>(&A[(size_t)row * 256 + k]);
    uint2 vh, vl;
    split4(a, vh, vl);
    *reinterpret_cast<uint2*>(&g_ap[(size_t)row * 512 + k]) = vh;
    *reinterpret_cast<uint2*>(&g_ap[(size_t)row * 512 + 256 + k]) = vl;
}

// ---------------- HMMA GEMM: C[M,256] = A'[M,768'] @ W'[N,768]^T ----------------
// 3-stage cp.async pipeline, one __syncthreads per chunk.
#define NCHUNK 12
#define STG_SZ 32768
__global__ __launch_bounds__(256) void k_mma(int wbase, float* __restrict__ C0,
                                             float* __restrict__ C1, int M) {
    extern __shared__ char smem[];
    const uint32_t sb = smem_u32(smem);
    const int tid = threadIdx.x, lane = tid & 31, wid = tid >> 5;
    const int warpM = wid >> 2, warpN = wid & 3;
    const int br = blockIdx.x * 128;
    const int ybase = blockIdx.y * 128;
    const __nv_bfloat16* Bp = g_wt + ((size_t)(wbase + blockIdx.z) * 256 + ybase) * KP;
    float* C = blockIdx.z ? C1 : C0;

    float acc[4][4][4];
#pragma unroll
    for (int i = 0; i < 4; i++)
#pragma unroll
        for (int j = 0; j < 4; j++)
#pragma unroll
            for (int q = 0; q < 4; q++) acc[i][j][q] = 0.f;

    auto load_chunk = [&](int c, int stage) {
        int aoff = (c < 4) ? c * 64 : (c < 8) ? (c - 4) * 64 : 256 + (c - 8) * 64;
        int boff = c * 64;
        uint32_t sA = sb + stage * STG_SZ;
        uint32_t sB = sA + 16384;
#pragma unroll
        for (int i = 0; i < 4; i++) {
            int idx = tid + i * 256;
            int row = idx >> 3;
            int cb = (idx & 7) * 16;
            int ar = br + row;
            if (ar >= M) ar = M - 1;
            const char* srcA = (const char*)(g_ap + (size_t)ar * 512 + aoff) + cb;
            uint32_t dA = sA + SMEM_SWZ(row * 128 + cb);
            asm volatile("cp.async.cg.shared.global [%0], [%1], 16;" :: "r"(dA), "l"(srcA));
            const char* srcB = (const char*)(Bp + (size_t)row * KP + boff) + cb;
            uint32_t dB = sB + SMEM_SWZ(row * 128 + cb);
            asm volatile("cp.async.cg.shared.global [%0], [%1], 16;" :: "r"(dB), "l"(srcB));
        }
        asm volatile("cp.async.commit_group;");
    };

    // prologue: 2 chunks in flight
    load_chunk(0, 0);
    load_chunk(1, 1);

    const int alr = lane & 15, aks = lane >> 4;
    const int bro = (lane & 7) + ((lane >> 4) << 3);
    const int bko = ((lane >> 3) & 1) * 16;

    for (int c = 0; c < NCHUNK; c++) {
        if (c < NCHUNK - 1)
            asm volatile("cp.async.wait_group 1;");
        else
            asm volatile("cp.async.wait_group 0;");
        __syncthreads();                       // stage c visible to all; all warps past compute c-1
        if (c + 2 < NCHUNK) load_chunk(c + 2, (c + 2) % 3);  // overwrites stage read at iter c-1
        uint32_t sA = sb + (c % 3) * STG_SZ;
        uint32_t sB = sA + 16384;
#pragma unroll
        for (int ks = 0; ks < 4; ks++) {
            int kb = ks * 32;
            uint32_t a[4][4], b[2][4];
#pragma unroll
            for (int mi = 0; mi < 4; mi++) {
                int row = warpM * 64 + mi * 16 + alr;
                uint32_t ad = sA + SMEM_SWZ(row * 128 + kb + aks * 16);
                asm volatile("ldmatrix.sync.aligned.m8n8.x4.shared.b16 {%0,%1,%2,%3}, [%4];"
                             : "=r"(a[mi][0]), "=r"(a[mi][1]), "=r"(a[mi][2]), "=r"(a[mi][3])
                             : "r"(ad));
            }
#pragma unroll
            for (int nj = 0; nj < 2; nj++) {
                int row = warpN * 32 + nj * 16 + bro;
                uint32_t bd = sB + SMEM_SWZ(row * 128 + kb + bko);
                asm volatile("ldmatrix.sync.aligned.m8n8.x4.shared.b16 {%0,%1,%2,%3}, [%4];"
                             : "=r"(b[nj][0]), "=r"(b[nj][1]), "=r"(b[nj][2]), "=r"(b[nj][3])
                             : "r"(bd));
            }
#pragma unroll
            for (int mi = 0; mi < 4; mi++)
#pragma unroll
                for (int n8 = 0; n8 < 4; n8++) {
                    uint32_t b0 = b[n8 >> 1][(n8 & 1) * 2];
                    uint32_t b1 = b[n8 >> 1][(n8 & 1) * 2 + 1];
                    asm volatile(
                        "mma.sync.aligned.m16n8k16.row.col.f32.bf16.bf16.f32 "
                        "{%0,%1,%2,%3}, {%4,%5,%6,%7}, {%8,%9}, {%0,%1,%2,%3};"
                        : "+f"(acc[mi][n8][0]), "+f"(acc[mi][n8][1]),
                          "+f"(acc[mi][n8][2]), "+f"(acc[mi][n8][3])
                        : "r"(a[mi][0]), "r"(a[mi][1]), "r"(a[mi][2]), "r"(a[mi][3]),
                          "r"(b0), "r"(b1));
                }
        }
        __syncthreads();  // all warps done reading stage c before it is refilled at iter c+1
    }

    int g = lane >> 2, c2 = (lane & 3) * 2;
#pragma unroll
    for (int mi = 0; mi < 4; mi++) {
        int r0 = br + warpM * 64 + mi * 16 + g;
#pragma unroll
        for (int n8 = 0; n8 < 4; n8++) {
            int col = ybase + warpN * 32 + n8 * 8 + c2;
            if (r0 < M) {
                C[(size_t)r0 * 256 + col] = acc[mi][n8][0];
                C[(size_t)r0 * 256 + col + 1] = acc[mi][n8][1];
            }
            if (r0 + 8 < M) {
                C[(size_t)(r0 + 8) * 256 + col] = acc[mi][n8][2];
                C[(size_t)(r0 + 8) * 256 + col + 1] = acc[mi][n8][3];
            }
        }
    }
}

// ---------------- score pass ----------------
__global__ void k_score(const void* __restrict__ ei,
                        const float* __restrict__ att, int E, int N) {
    int warp = (blockIdx.x * blockDim.x + threadIdx.x) >> 5;
    int lane = threadIdx.x & 31;
    int et = E + N;
    if (warp >= et) return;
    int src, dst;
    if (warp < E) { src = load_idx(ei, warp); dst = load_idx(ei, E + warp); }
    else          { src = dst = warp - E; }
    const float* xls = g_xl + (size_t)src * HC;
    const float* xrd = g_xr + (size_t)dst * HC;
    float pv[4];
#pragma unroll
    for (int h = 0; h < 4; h++) {
        int c0 = h * 64 + lane;
        float s0 = xls[c0] + xrd[c0];
        float s1 = xls[c0 + 32] + xrd[c0 + 32];
        s0 = s0 > 0.f ? s0 : 0.2f * s0;
        s1 = s1 > 0.f ? s1 : 0.2f * s1;
        float p = __ldg(&att[h * 64 + lane]) * s0 + __ldg(&att[h * 64 + lane + 32]) * s1;
#pragma unroll
        for (int o = 16; o; o >>= 1) p += __shfl_xor_sync(0xFFFFFFFFu, p, o);
        pv[h] = p;
    }
    if (lane == 0) {
        float4 ev = make_float4(__expf(pv[0]), __expf(pv[1]), __expf(pv[2]), __expf(pv[3]));
        *reinterpret_cast<float4*>(&g_score[(size_t)warp * 4]) = ev;
    }
}

// ---------------- gather: softmax-weighted aggregate + bias + relu ----------------
// writeSplit=1: emit bf16 hi/lo split directly into g_ap (next layer's GEMM input)
__global__ void k_gather(const float* __restrict__ bias, float* __restrict__ outp,
                         int n, int writeSplit) {
    int warp = (blockIdx.x * blockDim.x + threadIdx.x) >> 5;
    int lane = threadIdx.x & 31;
    if (warp >= n) return;
    int beg = g_off[warp];
    int end = g_off[warp + 1];
    int hi = lane >> 4;
    float4 a0 = make_float4(0.f, 0.f, 0.f, 0.f);
    float4 a1 = make_float4(0.f, 0.f, 0.f, 0.f);
    float d0 = 0.f, d1 = 0.f;
    const float4* XL = reinterpret_cast<const float4*>(g_xl);
    for (int e = beg; e < end; e++) {
        int src = g_csr_src[e];
        int eid = g_csr_eid[e];
        float4 sv = *reinterpret_cast<const float4*>(&g_score[(size_t)eid * 4]);
        float s0 = hi ? sv.y : sv.x;
        float s1 = hi ? sv.w : sv.z;
        float4 v0 = XL[(size_t)src * 64 + lane];
        float4 v1 = XL[(size_t)src * 64 + 32 + lane];
        a0.x += s0 * v0.x; a0.y += s0 * v0.y; a0.z += s0 * v0.z; a0.w += s0 * v0.w;
        a1.x += s1 * v1.x; a1.y += s1 * v1.y; a1.z += s1 * v1.z; a1.w += s1 * v1.w;
        d0 += s0;
        d1 += s1;
    }
    float i0 = 1.f / d0, i1 = 1.f / d1;
    const float4* B4 = reinterpret_cast<const float4*>(bias);
    float4 b0 = B4[lane], b1 = B4[32 + lane];
    float4 o0, o1;
    o0.x = fmaxf(a0.x * i0 + b0.x, 0.f); o0.y = fmaxf(a0.y * i0 + b0.y, 0.f);
    o0.z = fmaxf(a0.z * i0 + b0.z, 0.f); o0.w = fmaxf(a0.w * i0 + b0.w, 0.f);
    o1.x = fmaxf(a1.x * i1 + b1.x, 0.f); o1.y = fmaxf(a1.y * i1 + b1.y, 0.f);
    o1.z = fmaxf(a1.z * i1 + b1.z, 0.f); o1.w = fmaxf(a1.w * i1 + b1.w, 0.f);
    if (writeSplit) {
        uint2 vh0, vl0, vh1, vl1;
        split4(o0, vh0, vl0);
        split4(o1, vh1, vl1);
        __nv_bfloat16* ap = g_ap + (size_t)warp * 512;
        int c0 = lane * 4, c1 = 128 + lane * 4;
        *reinterpret_cast<uint2*>(ap + c0) = vh0;
        *reinterpret_cast<uint2*>(ap + c1) = vh1;
        *reinterpret_cast<uint2*>(ap + 256 + c0) = vl0;
        *reinterpret_cast<uint2*>(ap + 256 + c1) = vl1;
    } else {
        float4* O = reinterpret_cast<float4*>(outp);
        O[(size_t)warp * 64 + lane] = o0;
        O[(size_t)warp * 64 + 32 + lane] = o1;
    }
}

// ---------------- readout ----------------
__global__ void k_mean(const float* __restrict__ src, int n) {
    int col = threadIdx.x;
    float acc = 0.f;
    for (int r = blockIdx.x; r < n; r += gridDim.x)
        acc += src[(size_t)r * HC + col];
    atomicAdd(&g_gvec[col], acc);
}
__global__ void k_fc(const float* __restrict__ Wfc, const float* __restrict__ bfc,
                     float* __restrict__ out, int n) {
    int lane = threadIdx.x & 31;
    int w = threadIdx.x >> 5;
    if (w >= 2) return;
    float acc = 0.f;
    for (int c = lane; c < HC; c += 32) acc += g_gvec[c] * Wfc[c * 2 + w];
#pragma unroll
    for (int o = 16; o; o >>= 1) acc += __shfl_xor_sync(0xFFFFFFFFu, acc, o);
    if (lane == 0) out[w] = acc / (float)n + bfc[w];
}

// ---------------- launch ----------------
extern "C" void kernel_launch(void* const* d_in, const int* in_sizes, int n_in,
                              void* d_out, int out_size) {
    const float* x   = (const float*)d_in[0];
    const void*  ei  = d_in[1];
    const float* Wl1 = (const float*)d_in[2];
    const float* Wr1 = (const float*)d_in[3];
    const float* att1= (const float*)d_in[4];
    const float* b1  = (const float*)d_in[5];
    const float* Wl2 = (const float*)d_in[6];
    const float* Wr2 = (const float*)d_in[7];
    const float* att2= (const float*)d_in[8];
    const float* b2  = (const float*)d_in[9];
    const float* Wfc = (const float*)d_in[10];
    const float* bfc = (const float*)d_in[11];
    float* out       = (float*)d_out;

    int n = in_sizes[0] / HC;  // 20000
    int e = in_sizes[1] / 2;   // 320000
    int et = e + n;
    int nb = (n + 255) / 256;

    float *p_xl, *p_xr, *p_o2;
    cudaGetSymbolAddress((void**)&p_xl, g_xl);
    cudaGetSymbolAddress((void**)&p_xr, g_xr);
    cudaGetSymbolAddress((void**)&p_o2, g_o2);

    cudaFuncSetAttribute(k_mma, cudaFuncAttributeMaxDynamicSharedMemorySize, 3 * STG_SZ);

    dim3 gMma((n + 127) / 128, 2, 2);
    int bEdgeWarp = (et * 32 + 255) / 256;
    int bNodeWarp = (n * 32 + 255) / 256;
    int bSplit = (n * 64 + 255) / 256;

    // ---- setup ----
    k_detect<<<1, 32>>>((const int*)ei);
    k_wsplit<<<dim3(8, 8, 4), dim3(32, 8)>>>(Wl1, Wr1, Wl2, Wr2);
    k_zero<<<(n + 255) / 256, 256>>>(n);
    k_count<<<(e + 255) / 256, 256>>>(ei, e);
    k_scanA<<<nb, 256>>>(n);
    k_scanB<<<1, 32>>>(nb);
    k_scanC<<<nb, 256>>>(n);
    k_fill<<<(et + 255) / 256, 256>>>(ei, e, n);

    // ---- layer 1 ----
    k_asplit<<<bSplit, 256>>>(x, n);
    k_mma<<<gMma, 256, 3 * STG_SZ>>>(0, p_xl, p_xr, n);
    k_score<<<bEdgeWarp, 256>>>(ei, att1, e, n);
    k_gather<<<bNodeWarp, 256>>>(b1, nullptr, n, 1);   // writes bf16 split into g_ap

    // ---- layer 2 ----
    k_mma<<<gMma, 256, 3 * STG_SZ>>>(2, p_xl, p_xr, n);
    k_score<<<bEdgeWarp, 256>>>(ei, att2, e, n);
    k_gather<<<bNodeWarp, 256>>>(b2, p_o2, n, 0);

    // ---- readout ----
    k_mean<<<256, 256>>>(p_o2, n);
    k_fc<<<1, 64>>>(Wfc, bfc, out, n);
}